// round 11
// baseline (speedup 1.0000x reference)
#include <cuda_runtime.h>
#include <cstdint>
#include <cmath>

// ---------------- problem constants ----------------
#define N_NODES   20000
#define N_EDGES   320000
#define N_GRAPHS  200
#define MAXN      100
#define NPAIR     4950          // 100*99/2
#define IN_DIM    128
#define H_DIM     256
#define L_DIM     64

// ---------------- scratch (device globals; no allocation allowed) ----------
__device__ __align__(128) int   g_hist[N_NODES];            // in-degree
__device__ __align__(128) int   g_off [N_NODES];            // CSR exclusive offsets
__device__ __align__(128) int   g_cur [N_NODES];            // fill cursors
__device__ __align__(128) int   g_csr [N_EDGES];            // src ids grouped by dst
__device__ __align__(128) float g_dinv[N_NODES];            // rsqrt(deg+1)
__device__ __align__(128) float g_ax  [N_NODES * IN_DIM];   // aggregated x (conv1)
__device__ __align__(128) float g_u   [N_NODES * H_DIM];    // (A@W)*dinv[row]
__device__ __align__(128) float g_h   [N_NODES * H_DIM];    // conv1 output
__device__ __align__(128) float g_sums[N_GRAPHS * H_DIM];
__device__ __align__(128) float g_cnt [N_GRAPHS];
__device__ __align__(128) float g_hg  [N_GRAPHS * H_DIM];
__device__ __align__(128) float g_z   [N_GRAPHS * L_DIM];
__device__ __align__(128) float g_d1  [N_GRAPHS * H_DIM];
__device__ __align__(128) float g_d2  [N_GRAPHS * H_DIM];
__device__ __align__(128) int   g_pi  [NPAIR];
__device__ __align__(128) int   g_pj  [NPAIR];

// ---------------- zero scratch ----------------
__global__ void zero_kernel() {
    int i = blockIdx.x * blockDim.x + threadIdx.x;
    if (i < N_NODES) { g_hist[i] = 0; g_cur[i] = 0; }
    if (i < N_GRAPHS * H_DIM) g_sums[i] = 0.f;
    if (i < N_GRAPHS) g_cnt[i] = 0.f;
}

// ---------------- CSR build ----------------
__global__ void hist_kernel(const int* __restrict__ dst) {
    int e = blockIdx.x * blockDim.x + threadIdx.x;
    if (e < N_EDGES) atomicAdd(&g_hist[dst[e]], 1);
}

#define SCAN_T 1024
#define SCAN_CH 20   // 1024*20 >= 20000
__global__ __launch_bounds__(SCAN_T)
void scan_kernel() {
    __shared__ int sp[SCAN_T];
    int t = threadIdx.x;
    int start = t * SCAN_CH;
    int s = 0;
#pragma unroll
    for (int c = 0; c < SCAN_CH; c++) {
        int i = start + c;
        if (i < N_NODES) s += g_hist[i];
    }
    sp[t] = s;
    __syncthreads();
    for (int off = 1; off < SCAN_T; off <<= 1) {
        int v = (t >= off) ? sp[t - off] : 0;
        __syncthreads();
        sp[t] += v;
        __syncthreads();
    }
    int base = sp[t] - s;
#pragma unroll
    for (int c = 0; c < SCAN_CH; c++) {
        int i = start + c;
        if (i < N_NODES) { g_off[i] = base; base += g_hist[i]; }
    }
    for (int i = t; i < N_NODES; i += SCAN_T)
        g_dinv[i] = rsqrtf((float)g_hist[i] + 1.0f);
}

__global__ void fill_kernel(const int* __restrict__ src, const int* __restrict__ dst) {
    int e = blockIdx.x * blockDim.x + threadIdx.x;
    if (e >= N_EDGES) return;
    int d = dst[e];
    int pos = atomicAdd(&g_cur[d], 1);
    g_csr[g_off[d] + pos] = src[e];
}

// ------- conv1 aggregate over raw x: ax[m] = dinv[m]*(dinv[m]*x[m] + Σ dinv[s]*x[s])
// 64-thread blocks, 2 nodes per block (32 threads/node, float4 over 128 feats)
__global__ __launch_bounds__(64)
void gather_x_kernel(const float* __restrict__ x) {
    int m  = blockIdx.x * 2 + (threadIdx.x >> 5);
    int f4 = threadIdx.x & 31;             // 0..31
    const float4* X4 = reinterpret_cast<const float4*>(x);
    int beg = g_off[m];
    int cnt = g_hist[m];
    float di = g_dinv[m];
    float4 xs = X4[(size_t)m * 32 + f4];
    float4 acc;
    acc.x = di * xs.x; acc.y = di * xs.y; acc.z = di * xs.z; acc.w = di * xs.w;
    int e = 0;
    for (; e + 4 <= cnt; e += 4) {
        int s0 = g_csr[beg + e + 0], s1 = g_csr[beg + e + 1];
        int s2 = g_csr[beg + e + 2], s3 = g_csr[beg + e + 3];
        float d0 = g_dinv[s0], d1 = g_dinv[s1], d2 = g_dinv[s2], d3 = g_dinv[s3];
        float4 v0 = X4[(size_t)s0 * 32 + f4];
        float4 v1 = X4[(size_t)s1 * 32 + f4];
        float4 v2 = X4[(size_t)s2 * 32 + f4];
        float4 v3 = X4[(size_t)s3 * 32 + f4];
        acc.x += d0 * v0.x + d1 * v1.x + d2 * v2.x + d3 * v3.x;
        acc.y += d0 * v0.y + d1 * v1.y + d2 * v2.y + d3 * v3.y;
        acc.z += d0 * v0.z + d1 * v1.z + d2 * v2.z + d3 * v3.z;
        acc.w += d0 * v0.w + d1 * v1.w + d2 * v2.w + d3 * v3.w;
    }
    for (; e < cnt; e++) {
        int s = g_csr[beg + e];
        float ds = g_dinv[s];
        float4 v = X4[(size_t)s * 32 + f4];
        acc.x += ds * v.x; acc.y += ds * v.y; acc.z += ds * v.z; acc.w += ds * v.w;
    }
    acc.x *= di; acc.y *= di; acc.z *= di; acc.w *= di;
    reinterpret_cast<float4*>(g_ax)[(size_t)m * 32 + f4] = acc;
}

// ---------------- GEMM: U = (A@B) * dinv[row], register-prefetch pipelined --
// (unchanged, proven — used for conv2)
#define TBM 128
#define TBN 128
#define TBK 8
__global__ __launch_bounds__(256)
void gemm_rowscale_kernel(const float* __restrict__ A,
                          const float* __restrict__ B,
                          float* __restrict__ U,
                          int M, int K, int N) {
    __shared__ float As[TBK][TBM];
    __shared__ float Bs[TBK][TBN];
    const int bm  = blockIdx.y * TBM;
    const int bn  = blockIdx.x * TBN;
    const int tid = threadIdx.x;
    const int tx  = tid & 15;
    const int ty  = tid >> 4;

    const int lm  = tid >> 1;
    const int lk  = (tid & 1) * 4;
    const int bkk = tid >> 5;
    const int bnn = (tid & 31) * 4;

    float acc[8][8];
#pragma unroll
    for (int i = 0; i < 8; i++)
#pragma unroll
        for (int j = 0; j < 8; j++) acc[i][j] = 0.f;

    float4 av = make_float4(0.f, 0.f, 0.f, 0.f);
    if (bm + lm < M)
        av = *reinterpret_cast<const float4*>(&A[(size_t)(bm + lm) * K + lk]);
    float4 bv = *reinterpret_cast<const float4*>(&B[(size_t)bkk * N + bn + bnn]);

    for (int k0 = 0; k0 < K; k0 += TBK) {
        As[lk + 0][lm] = av.x; As[lk + 1][lm] = av.y;
        As[lk + 2][lm] = av.z; As[lk + 3][lm] = av.w;
        *reinterpret_cast<float4*>(&Bs[bkk][bnn]) = bv;
        __syncthreads();

        if (k0 + TBK < K) {
            av = make_float4(0.f, 0.f, 0.f, 0.f);
            if (bm + lm < M)
                av = *reinterpret_cast<const float4*>(&A[(size_t)(bm + lm) * K + k0 + TBK + lk]);
            bv = *reinterpret_cast<const float4*>(&B[(size_t)(k0 + TBK + bkk) * N + bn + bnn]);
        }

#pragma unroll
        for (int kk = 0; kk < TBK; kk++) {
            float a[8], b[8];
#pragma unroll
            for (int i = 0; i < 8; i++) a[i] = As[kk][ty * 8 + i];
#pragma unroll
            for (int j = 0; j < 8; j++) b[j] = Bs[kk][tx * 8 + j];
#pragma unroll
            for (int i = 0; i < 8; i++)
#pragma unroll
                for (int j = 0; j < 8; j++) acc[i][j] += a[i] * b[j];
        }
        __syncthreads();
    }

#pragma unroll
    for (int i = 0; i < 8; i++) {
        int m = bm + ty * 8 + i;
        if (m >= M) continue;
        float rs = g_dinv[m];
#pragma unroll
        for (int j = 0; j < 8; j += 4) {
            int n = bn + tx * 8 + j;
            float4 v;
            v.x = acc[i][j + 0] * rs; v.y = acc[i][j + 1] * rs;
            v.z = acc[i][j + 2] * rs; v.w = acc[i][j + 3] * rs;
            *reinterpret_cast<float4*>(&U[(size_t)m * N + n]) = v;
        }
    }
}

// ---- same GEMM body, epilogue = relu(acc + bias)  (conv1 transform) ------
__global__ __launch_bounds__(256)
void gemm_bias_relu_kernel(const float* __restrict__ A,
                           const float* __restrict__ B,
                           const float* __restrict__ bias,
                           float* __restrict__ O,
                           int M, int K, int N) {
    __shared__ float As[TBK][TBM];
    __shared__ float Bs[TBK][TBN];
    const int bm  = blockIdx.y * TBM;
    const int bn  = blockIdx.x * TBN;
    const int tid = threadIdx.x;
    const int tx  = tid & 15;
    const int ty  = tid >> 4;

    const int lm  = tid >> 1;
    const int lk  = (tid & 1) * 4;
    const int bkk = tid >> 5;
    const int bnn = (tid & 31) * 4;

    float acc[8][8];
#pragma unroll
    for (int i = 0; i < 8; i++)
#pragma unroll
        for (int j = 0; j < 8; j++) acc[i][j] = 0.f;

    float4 av = make_float4(0.f, 0.f, 0.f, 0.f);
    if (bm + lm < M)
        av = *reinterpret_cast<const float4*>(&A[(size_t)(bm + lm) * K + lk]);
    float4 bv = *reinterpret_cast<const float4*>(&B[(size_t)bkk * N + bn + bnn]);

    for (int k0 = 0; k0 < K; k0 += TBK) {
        As[lk + 0][lm] = av.x; As[lk + 1][lm] = av.y;
        As[lk + 2][lm] = av.z; As[lk + 3][lm] = av.w;
        *reinterpret_cast<float4*>(&Bs[bkk][bnn]) = bv;
        __syncthreads();

        if (k0 + TBK < K) {
            av = make_float4(0.f, 0.f, 0.f, 0.f);
            if (bm + lm < M)
                av = *reinterpret_cast<const float4*>(&A[(size_t)(bm + lm) * K + k0 + TBK + lk]);
            bv = *reinterpret_cast<const float4*>(&B[(size_t)(k0 + TBK + bkk) * N + bn + bnn]);
        }

#pragma unroll
        for (int kk = 0; kk < TBK; kk++) {
            float a[8], b[8];
#pragma unroll
            for (int i = 0; i < 8; i++) a[i] = As[kk][ty * 8 + i];
#pragma unroll
            for (int j = 0; j < 8; j++) b[j] = Bs[kk][tx * 8 + j];
#pragma unroll
            for (int i = 0; i < 8; i++)
#pragma unroll
                for (int j = 0; j < 8; j++) acc[i][j] += a[i] * b[j];
        }
        __syncthreads();
    }

#pragma unroll
    for (int i = 0; i < 8; i++) {
        int m = bm + ty * 8 + i;
        if (m >= M) continue;
#pragma unroll
        for (int j = 0; j < 8; j += 4) {
            int n = bn + tx * 8 + j;
            float4 bb = *reinterpret_cast<const float4*>(&bias[n]);
            float4 v;
            v.x = fmaxf(acc[i][j + 0] + bb.x, 0.f);
            v.y = fmaxf(acc[i][j + 1] + bb.y, 0.f);
            v.z = fmaxf(acc[i][j + 2] + bb.z, 0.f);
            v.w = fmaxf(acc[i][j + 3] + bb.w, 0.f);
            *reinterpret_cast<float4*>(&O[(size_t)m * N + n]) = v;
        }
    }
}

// conv2 gather fused with mean-pool accumulation (h never materialized)
__global__ __launch_bounds__(64)
void gather_pool_kernel(const float* __restrict__ bias, const int* __restrict__ batch) {
    int m = blockIdx.x;
    int f4 = threadIdx.x;
    const float4* U4 = reinterpret_cast<const float4*>(g_u);
    int beg = g_off[m];
    int cnt = g_hist[m];
    float4 acc = U4[(size_t)m * 64 + f4];
    int e = 0;
    for (; e + 4 <= cnt; e += 4) {
        int s0 = g_csr[beg + e + 0], s1 = g_csr[beg + e + 1];
        int s2 = g_csr[beg + e + 2], s3 = g_csr[beg + e + 3];
        float4 v0 = U4[(size_t)s0 * 64 + f4];
        float4 v1 = U4[(size_t)s1 * 64 + f4];
        float4 v2 = U4[(size_t)s2 * 64 + f4];
        float4 v3 = U4[(size_t)s3 * 64 + f4];
        acc.x += (v0.x + v1.x) + (v2.x + v3.x);
        acc.y += (v0.y + v1.y) + (v2.y + v3.y);
        acc.z += (v0.z + v1.z) + (v2.z + v3.z);
        acc.w += (v0.w + v1.w) + (v2.w + v3.w);
    }
    for (; e < cnt; e++) {
        int s = g_csr[beg + e];
        float4 v = U4[(size_t)s * 64 + f4];
        acc.x += v.x; acc.y += v.y; acc.z += v.z; acc.w += v.w;
    }
    float di = g_dinv[m];
    float4 bb = reinterpret_cast<const float4*>(bias)[f4];
    float hx = fmaxf(di * acc.x + bb.x, 0.f);
    float hy = fmaxf(di * acc.y + bb.y, 0.f);
    float hz = fmaxf(di * acc.z + bb.z, 0.f);
    float hw = fmaxf(di * acc.w + bb.w, 0.f);
    int b = batch[m];
    float* sbase = &g_sums[(size_t)b * H_DIM + f4 * 4];
    atomicAdd(sbase + 0, hx);
    atomicAdd(sbase + 1, hy);
    atomicAdd(sbase + 2, hz);
    atomicAdd(sbase + 3, hw);
    if (f4 == 0) atomicAdd(&g_cnt[b], 1.0f);
}

__global__ void pool_div_kernel() {
    int g = blockIdx.x;
    int f = threadIdx.x;
    g_hg[g * H_DIM + f] = g_sums[g * H_DIM + f] / fmaxf(g_cnt[g], 1.0f);
}

// ---------------- mu / logvar / z ----------------
__global__ void muz_kernel(const float* __restrict__ Wmu, const float* __restrict__ bmu,
                           const float* __restrict__ Wlv, const float* __restrict__ blv,
                           const float* __restrict__ eps,
                           float* __restrict__ out_mu, float* __restrict__ out_lv) {
    int g = blockIdx.x;
    int l = threadIdx.x;            // 64
    __shared__ float sh[H_DIM];
    for (int k = l; k < H_DIM; k += L_DIM) sh[k] = g_hg[g * H_DIM + k];
    __syncthreads();
    float mu = bmu[l], lv = blv[l];
    for (int k = 0; k < H_DIM; k++) {
        float h = sh[k];
        mu += h * Wmu[k * L_DIM + l];
        lv += h * Wlv[k * L_DIM + l];
    }
    out_mu[g * L_DIM + l] = mu;
    out_lv[g * L_DIM + l] = lv;
    g_z[g * L_DIM + l] = mu + eps[g * L_DIM + l] * expf(0.5f * lv);
}

// ---------------- decoder dense+relu ----------------
__global__ void dense_relu_kernel(const float* __restrict__ X,
                                  const float* __restrict__ W,
                                  const float* __restrict__ b,
                                  float* __restrict__ Y, int K) {
    int g = blockIdx.x;
    int n = threadIdx.x;            // 256
    __shared__ float sx[H_DIM];
    if (n < K) sx[n] = X[g * K + n];
    __syncthreads();
    float acc = b[n];
    for (int k = 0; k < K; k++) acc += sx[k] * W[k * H_DIM + n];
    Y[g * H_DIM + n] = fmaxf(acc, 0.f);
}

// ---------------- adjacency decode ----------------
__global__ void pairmap_kernel() {
    int i = blockIdx.x;             // 0..99
    int j = threadIdx.x;            // 0..127
    if (j > i && j < MAXN) {
        int p = i * 99 - (i * (i - 1)) / 2 + (j - i - 1);
        g_pi[p] = i;
        g_pj[p] = j;
    }
}

__global__ void diag_kernel(float* __restrict__ adj) {
    int g = blockIdx.x;
    int i = threadIdx.x;
    if (i < MAXN)
        adj[(size_t)g * MAXN * MAXN + i * MAXN + i] = 0.f;
}

#define GCH 8
__global__ __launch_bounds__(128)
void adj_kernel(const float* __restrict__ D3, const float* __restrict__ db3,
                float* __restrict__ adj) {
    int p  = blockIdx.x * 128 + threadIdx.x;
    int g0 = blockIdx.y * GCH;
    __shared__ float sd2[GCH][H_DIM];
    for (int idx = threadIdx.x; idx < GCH * H_DIM; idx += 128)
        sd2[idx >> 8][idx & 255] = g_d2[(size_t)(g0 + (idx >> 8)) * H_DIM + (idx & 255)];
    __syncthreads();
    if (p >= NPAIR) return;
    int i = g_pi[p], j = g_pj[p];
    float bb = db3[p];
    float acc[GCH];
#pragma unroll
    for (int gg = 0; gg < GCH; gg++) acc[gg] = bb;
    for (int k = 0; k < H_DIM; k++) {
        float w = D3[(size_t)k * NPAIR + p];
#pragma unroll
        for (int gg = 0; gg < GCH; gg++) acc[gg] += sd2[gg][k] * w;
    }
#pragma unroll
    for (int gg = 0; gg < GCH; gg++) {
        float prob = 1.0f / (1.0f + expf(-acc[gg]));
        size_t base = (size_t)(g0 + gg) * (MAXN * MAXN);
        adj[base + i * MAXN + j] = prob;
        adj[base + j * MAXN + i] = prob;
    }
}

// ---------------- launch ----------------
extern "C" void kernel_launch(void* const* d_in, const int* in_sizes, int n_in,
                              void* d_out, int out_size) {
    const float* x    = (const float*)d_in[0];
    const int*   ei   = (const int*)  d_in[1];
    const int*   batch= (const int*)  d_in[2];
    const float* eps  = (const float*)d_in[3];
    const float* W1   = (const float*)d_in[4];
    const float* b1   = (const float*)d_in[5];
    const float* W2   = (const float*)d_in[6];
    const float* b2   = (const float*)d_in[7];
    const float* Wmu  = (const float*)d_in[8];
    const float* bmu  = (const float*)d_in[9];
    const float* Wlv  = (const float*)d_in[10];
    const float* blv  = (const float*)d_in[11];
    const float* D1   = (const float*)d_in[12];
    const float* db1  = (const float*)d_in[13];
    const float* D2   = (const float*)d_in[14];
    const float* db2  = (const float*)d_in[15];
    const float* D3   = (const float*)d_in[16];
    const float* db3  = (const float*)d_in[17];

    const int* src = ei;
    const int* dst = ei + N_EDGES;

    float* out      = (float*)d_out;
    float* out_adj  = out;                                        // 200*100*100
    float* out_mu   = out + (size_t)N_GRAPHS * MAXN * MAXN;       // 200*64
    float* out_lv   = out_mu + (size_t)N_GRAPHS * L_DIM;          // 200*64

    float *p_ax, *p_u, *p_h, *p_z, *p_d1, *p_d2;
    cudaGetSymbolAddress((void**)&p_ax, g_ax);
    cudaGetSymbolAddress((void**)&p_u,  g_u);
    cudaGetSymbolAddress((void**)&p_h,  g_h);
    cudaGetSymbolAddress((void**)&p_z,  g_z);
    cudaGetSymbolAddress((void**)&p_d1, g_d1);
    cudaGetSymbolAddress((void**)&p_d2, g_d2);

    // CSR build (also computes dinv) + zero pool buffers
    zero_kernel<<<(N_GRAPHS * H_DIM + 255) / 256, 256>>>();
    hist_kernel<<<(N_EDGES + 255) / 256, 256>>>(dst);
    scan_kernel<<<1, SCAN_T>>>();
    fill_kernel<<<(N_EDGES + 255) / 256, 256>>>(src, dst);
    pairmap_kernel<<<MAXN, 128>>>();

    dim3 ggrid(H_DIM / TBN, (N_NODES + TBM - 1) / TBM);

    // conv1: aggregate raw x (128-dim gather), then transform + bias + relu
    gather_x_kernel<<<N_NODES / 2, 64>>>(x);
    gemm_bias_relu_kernel<<<ggrid, 256>>>(p_ax, W1, b1, p_h, N_NODES, IN_DIM, H_DIM);

    // conv2: gemm (dinv folded) -> gather fused with mean-pool accumulation
    gemm_rowscale_kernel<<<ggrid, 256>>>(p_h, W2, p_u, N_NODES, H_DIM, H_DIM);
    gather_pool_kernel<<<N_NODES, 64>>>(b2, batch);
    pool_div_kernel<<<N_GRAPHS, H_DIM>>>();

    // VAE head
    muz_kernel<<<N_GRAPHS, L_DIM>>>(Wmu, bmu, Wlv, blv, eps, out_mu, out_lv);

    // decoder MLP
    dense_relu_kernel<<<N_GRAPHS, H_DIM>>>(p_z,  D1, db1, p_d1, L_DIM);
    dense_relu_kernel<<<N_GRAPHS, H_DIM>>>(p_d1, D2, db2, p_d2, H_DIM);

    // adjacency
    diag_kernel<<<N_GRAPHS, 128>>>(out_adj);
    adj_kernel<<<dim3((NPAIR + 127) / 128, N_GRAPHS / GCH), 128>>>(D3, db3, out_adj);
}

// round 12
// speedup vs baseline: 1.1271x; 1.1271x over previous
#include <cuda_runtime.h>
#include <cstdint>
#include <cmath>

// ---------------- problem constants ----------------
#define N_NODES   20000
#define N_EDGES   320000
#define N_GRAPHS  200
#define MAXN      100
#define NPAIR     4950          // 100*99/2
#define IN_DIM    128
#define H_DIM     256
#define L_DIM     64

// ---------------- scratch (device globals; no allocation allowed) ----------
__device__ __align__(128) int   g_hist[N_NODES];            // in-degree
__device__ __align__(128) int   g_off [N_NODES];            // CSR exclusive offsets
__device__ __align__(128) int   g_cur [N_NODES];            // fill cursors
__device__ __align__(128) int   g_csr [N_EDGES];            // src ids grouped by dst
__device__ __align__(128) float g_dinv[N_NODES];            // rsqrt(deg+1)
__device__ __align__(128) float g_u   [N_NODES * H_DIM];    // (A@W)*dinv[row]
__device__ __align__(128) float g_h   [N_NODES * H_DIM];    // conv1 output
__device__ __align__(128) float g_sums[N_GRAPHS * H_DIM];
__device__ __align__(128) float g_cnt [N_GRAPHS];
__device__ __align__(128) float g_hg  [N_GRAPHS * H_DIM];
__device__ __align__(128) float g_z   [N_GRAPHS * L_DIM];
__device__ __align__(128) float g_d1  [N_GRAPHS * H_DIM];
__device__ __align__(128) float g_d2  [N_GRAPHS * H_DIM];
__device__ __align__(128) int   g_pi  [NPAIR];
__device__ __align__(128) int   g_pj  [NPAIR];

// ---------------- zero scratch ----------------
__global__ void zero_kernel() {
    int i = blockIdx.x * blockDim.x + threadIdx.x;
    if (i < N_NODES) { g_hist[i] = 0; g_cur[i] = 0; }
    if (i < N_GRAPHS * H_DIM) g_sums[i] = 0.f;
    if (i < N_GRAPHS) g_cnt[i] = 0.f;
}

// ---------------- CSR build ----------------
__global__ void hist_kernel(const int* __restrict__ dst) {
    int e = blockIdx.x * blockDim.x + threadIdx.x;
    if (e < N_EDGES) atomicAdd(&g_hist[dst[e]], 1);
}

#define SCAN_T 1024
#define SCAN_CH 20   // 1024*20 >= 20000
__global__ __launch_bounds__(SCAN_T)
void scan_kernel() {
    __shared__ int sp[SCAN_T];
    int t = threadIdx.x;
    int start = t * SCAN_CH;
    int s = 0;
#pragma unroll
    for (int c = 0; c < SCAN_CH; c++) {
        int i = start + c;
        if (i < N_NODES) s += g_hist[i];
    }
    sp[t] = s;
    __syncthreads();
    for (int off = 1; off < SCAN_T; off <<= 1) {
        int v = (t >= off) ? sp[t - off] : 0;
        __syncthreads();
        sp[t] += v;
        __syncthreads();
    }
    int base = sp[t] - s;
#pragma unroll
    for (int c = 0; c < SCAN_CH; c++) {
        int i = start + c;
        if (i < N_NODES) { g_off[i] = base; base += g_hist[i]; }
    }
    for (int i = t; i < N_NODES; i += SCAN_T)
        g_dinv[i] = rsqrtf((float)g_hist[i] + 1.0f);
}

__global__ void fill_kernel(const int* __restrict__ src, const int* __restrict__ dst) {
    int e = blockIdx.x * blockDim.x + threadIdx.x;
    if (e >= N_EDGES) return;
    int d = dst[e];
    int pos = atomicAdd(&g_cur[d], 1);
    g_csr[g_off[d] + pos] = src[e];
}

// ---------------- GEMM: U = (A@B) * dinv[row], register-prefetch pipelined --
#define TBM 128
#define TBN 128
#define TBK 8
__global__ __launch_bounds__(256)
void gemm_rowscale_kernel(const float* __restrict__ A,
                          const float* __restrict__ B,
                          float* __restrict__ U,
                          int M, int K, int N) {
    __shared__ float As[TBK][TBM];
    __shared__ float Bs[TBK][TBN];
    const int bm  = blockIdx.y * TBM;
    const int bn  = blockIdx.x * TBN;
    const int tid = threadIdx.x;
    const int tx  = tid & 15;
    const int ty  = tid >> 4;

    const int lm  = tid >> 1;            // A tile row
    const int lk  = (tid & 1) * 4;       // A tile k-offset
    const int bkk = tid >> 5;            // B tile k row
    const int bnn = (tid & 31) * 4;      // B tile col

    float acc[8][8];
#pragma unroll
    for (int i = 0; i < 8; i++)
#pragma unroll
        for (int j = 0; j < 8; j++) acc[i][j] = 0.f;

    float4 av = make_float4(0.f, 0.f, 0.f, 0.f);
    if (bm + lm < M)
        av = *reinterpret_cast<const float4*>(&A[(size_t)(bm + lm) * K + lk]);
    float4 bv = *reinterpret_cast<const float4*>(&B[(size_t)bkk * N + bn + bnn]);

    for (int k0 = 0; k0 < K; k0 += TBK) {
        As[lk + 0][lm] = av.x; As[lk + 1][lm] = av.y;
        As[lk + 2][lm] = av.z; As[lk + 3][lm] = av.w;
        *reinterpret_cast<float4*>(&Bs[bkk][bnn]) = bv;
        __syncthreads();

        if (k0 + TBK < K) {
            av = make_float4(0.f, 0.f, 0.f, 0.f);
            if (bm + lm < M)
                av = *reinterpret_cast<const float4*>(&A[(size_t)(bm + lm) * K + k0 + TBK + lk]);
            bv = *reinterpret_cast<const float4*>(&B[(size_t)(k0 + TBK + bkk) * N + bn + bnn]);
        }

#pragma unroll
        for (int kk = 0; kk < TBK; kk++) {
            float a[8], b[8];
#pragma unroll
            for (int i = 0; i < 8; i++) a[i] = As[kk][ty * 8 + i];
#pragma unroll
            for (int j = 0; j < 8; j++) b[j] = Bs[kk][tx * 8 + j];
#pragma unroll
            for (int i = 0; i < 8; i++)
#pragma unroll
                for (int j = 0; j < 8; j++) acc[i][j] += a[i] * b[j];
        }
        __syncthreads();
    }

#pragma unroll
    for (int i = 0; i < 8; i++) {
        int m = bm + ty * 8 + i;
        if (m >= M) continue;
        float rs = g_dinv[m];
#pragma unroll
        for (int j = 0; j < 8; j += 4) {
            int n = bn + tx * 8 + j;
            float4 v;
            v.x = acc[i][j + 0] * rs; v.y = acc[i][j + 1] * rs;
            v.z = acc[i][j + 2] * rs; v.w = acc[i][j + 3] * rs;
            *reinterpret_cast<float4*>(&U[(size_t)m * N + n]) = v;
        }
    }
}

// ---------------- CSR gather conv: h[m] = relu(dinv[m]*(u[m]+Σu[s]) + b) ---
// 64 threads per node, float4 per thread (256 features), edge loop unrolled x4
__global__ __launch_bounds__(64)
void gather_relu_kernel(const float* __restrict__ bias, float* __restrict__ out) {
    int m = blockIdx.x;
    int f4 = threadIdx.x;                  // 0..63
    const float4* U4 = reinterpret_cast<const float4*>(g_u);
    int beg = g_off[m];
    int cnt = g_hist[m];
    float4 acc = U4[(size_t)m * 64 + f4];  // self loop
    int e = 0;
    for (; e + 4 <= cnt; e += 4) {
        int s0 = g_csr[beg + e + 0], s1 = g_csr[beg + e + 1];
        int s2 = g_csr[beg + e + 2], s3 = g_csr[beg + e + 3];
        float4 v0 = U4[(size_t)s0 * 64 + f4];
        float4 v1 = U4[(size_t)s1 * 64 + f4];
        float4 v2 = U4[(size_t)s2 * 64 + f4];
        float4 v3 = U4[(size_t)s3 * 64 + f4];
        acc.x += (v0.x + v1.x) + (v2.x + v3.x);
        acc.y += (v0.y + v1.y) + (v2.y + v3.y);
        acc.z += (v0.z + v1.z) + (v2.z + v3.z);
        acc.w += (v0.w + v1.w) + (v2.w + v3.w);
    }
    for (; e < cnt; e++) {
        int s = g_csr[beg + e];
        float4 v = U4[(size_t)s * 64 + f4];
        acc.x += v.x; acc.y += v.y; acc.z += v.z; acc.w += v.w;
    }
    float di = g_dinv[m];
    float4 bb = reinterpret_cast<const float4*>(bias)[f4];
    float4 h;
    h.x = fmaxf(di * acc.x + bb.x, 0.f);
    h.y = fmaxf(di * acc.y + bb.y, 0.f);
    h.z = fmaxf(di * acc.z + bb.z, 0.f);
    h.w = fmaxf(di * acc.w + bb.w, 0.f);
    reinterpret_cast<float4*>(out)[(size_t)m * 64 + f4] = h;
}

// conv2 gather fused with mean-pool accumulation (h never materialized)
__global__ __launch_bounds__(64)
void gather_pool_kernel(const float* __restrict__ bias, const int* __restrict__ batch) {
    int m = blockIdx.x;
    int f4 = threadIdx.x;
    const float4* U4 = reinterpret_cast<const float4*>(g_u);
    int beg = g_off[m];
    int cnt = g_hist[m];
    float4 acc = U4[(size_t)m * 64 + f4];
    int e = 0;
    for (; e + 4 <= cnt; e += 4) {
        int s0 = g_csr[beg + e + 0], s1 = g_csr[beg + e + 1];
        int s2 = g_csr[beg + e + 2], s3 = g_csr[beg + e + 3];
        float4 v0 = U4[(size_t)s0 * 64 + f4];
        float4 v1 = U4[(size_t)s1 * 64 + f4];
        float4 v2 = U4[(size_t)s2 * 64 + f4];
        float4 v3 = U4[(size_t)s3 * 64 + f4];
        acc.x += (v0.x + v1.x) + (v2.x + v3.x);
        acc.y += (v0.y + v1.y) + (v2.y + v3.y);
        acc.z += (v0.z + v1.z) + (v2.z + v3.z);
        acc.w += (v0.w + v1.w) + (v2.w + v3.w);
    }
    for (; e < cnt; e++) {
        int s = g_csr[beg + e];
        float4 v = U4[(size_t)s * 64 + f4];
        acc.x += v.x; acc.y += v.y; acc.z += v.z; acc.w += v.w;
    }
    float di = g_dinv[m];
    float4 bb = reinterpret_cast<const float4*>(bias)[f4];
    float hx = fmaxf(di * acc.x + bb.x, 0.f);
    float hy = fmaxf(di * acc.y + bb.y, 0.f);
    float hz = fmaxf(di * acc.z + bb.z, 0.f);
    float hw = fmaxf(di * acc.w + bb.w, 0.f);
    int b = batch[m];
    float* sbase = &g_sums[(size_t)b * H_DIM + f4 * 4];
    atomicAdd(sbase + 0, hx);
    atomicAdd(sbase + 1, hy);
    atomicAdd(sbase + 2, hz);
    atomicAdd(sbase + 3, hw);
    if (f4 == 0) atomicAdd(&g_cnt[b], 1.0f);
}

__global__ void pool_div_kernel() {
    int g = blockIdx.x;
    int f = threadIdx.x;
    g_hg[g * H_DIM + f] = g_sums[g * H_DIM + f] / fmaxf(g_cnt[g], 1.0f);
}

// ---------------- mu / logvar / z ----------------
__global__ void muz_kernel(const float* __restrict__ Wmu, const float* __restrict__ bmu,
                           const float* __restrict__ Wlv, const float* __restrict__ blv,
                           const float* __restrict__ eps,
                           float* __restrict__ out_mu, float* __restrict__ out_lv) {
    int g = blockIdx.x;
    int l = threadIdx.x;            // 64
    __shared__ float sh[H_DIM];
    for (int k = l; k < H_DIM; k += L_DIM) sh[k] = g_hg[g * H_DIM + k];
    __syncthreads();
    float mu = bmu[l], lv = blv[l];
    for (int k = 0; k < H_DIM; k++) {
        float h = sh[k];
        mu += h * Wmu[k * L_DIM + l];
        lv += h * Wlv[k * L_DIM + l];
    }
    out_mu[g * L_DIM + l] = mu;
    out_lv[g * L_DIM + l] = lv;
    g_z[g * L_DIM + l] = mu + eps[g * L_DIM + l] * expf(0.5f * lv);
}

// ---------------- decoder dense+relu ----------------
__global__ void dense_relu_kernel(const float* __restrict__ X,
                                  const float* __restrict__ W,
                                  const float* __restrict__ b,
                                  float* __restrict__ Y, int K) {
    int g = blockIdx.x;
    int n = threadIdx.x;            // 256
    __shared__ float sx[H_DIM];
    if (n < K) sx[n] = X[g * K + n];
    __syncthreads();
    float acc = b[n];
    for (int k = 0; k < K; k++) acc += sx[k] * W[k * H_DIM + n];
    Y[g * H_DIM + n] = fmaxf(acc, 0.f);
}

// ---------------- adjacency decode ----------------
__global__ void pairmap_kernel() {
    int i = blockIdx.x;             // 0..99
    int j = threadIdx.x;            // 0..127
    if (j > i && j < MAXN) {
        int p = i * 99 - (i * (i - 1)) / 2 + (j - i - 1);
        g_pi[p] = i;
        g_pj[p] = j;
    }
}

__global__ void diag_kernel(float* __restrict__ adj) {
    int g = blockIdx.x;
    int i = threadIdx.x;
    if (i < MAXN)
        adj[(size_t)g * MAXN * MAXN + i * MAXN + i] = 0.f;
}

#define GCH 8
__global__ __launch_bounds__(128)
void adj_kernel(const float* __restrict__ D3, const float* __restrict__ db3,
                float* __restrict__ adj) {
    int p  = blockIdx.x * 128 + threadIdx.x;
    int g0 = blockIdx.y * GCH;
    __shared__ float sd2[GCH][H_DIM];
    for (int idx = threadIdx.x; idx < GCH * H_DIM; idx += 128)
        sd2[idx >> 8][idx & 255] = g_d2[(size_t)(g0 + (idx >> 8)) * H_DIM + (idx & 255)];
    __syncthreads();
    if (p >= NPAIR) return;
    int i = g_pi[p], j = g_pj[p];
    float bb = db3[p];
    float acc[GCH];
#pragma unroll
    for (int gg = 0; gg < GCH; gg++) acc[gg] = bb;
    for (int k = 0; k < H_DIM; k++) {
        float w = D3[(size_t)k * NPAIR + p];
#pragma unroll
        for (int gg = 0; gg < GCH; gg++) acc[gg] += sd2[gg][k] * w;
    }
#pragma unroll
    for (int gg = 0; gg < GCH; gg++) {
        float prob = 1.0f / (1.0f + expf(-acc[gg]));
        size_t base = (size_t)(g0 + gg) * (MAXN * MAXN);
        adj[base + i * MAXN + j] = prob;
        adj[base + j * MAXN + i] = prob;
    }
}

// ---------------- launch ----------------
extern "C" void kernel_launch(void* const* d_in, const int* in_sizes, int n_in,
                              void* d_out, int out_size) {
    const float* x    = (const float*)d_in[0];
    const int*   ei   = (const int*)  d_in[1];
    const int*   batch= (const int*)  d_in[2];
    const float* eps  = (const float*)d_in[3];
    const float* W1   = (const float*)d_in[4];
    const float* b1   = (const float*)d_in[5];
    const float* W2   = (const float*)d_in[6];
    const float* b2   = (const float*)d_in[7];
    const float* Wmu  = (const float*)d_in[8];
    const float* bmu  = (const float*)d_in[9];
    const float* Wlv  = (const float*)d_in[10];
    const float* blv  = (const float*)d_in[11];
    const float* D1   = (const float*)d_in[12];
    const float* db1  = (const float*)d_in[13];
    const float* D2   = (const float*)d_in[14];
    const float* db2  = (const float*)d_in[15];
    const float* D3   = (const float*)d_in[16];
    const float* db3  = (const float*)d_in[17];

    const int* src = ei;
    const int* dst = ei + N_EDGES;

    float* out      = (float*)d_out;
    float* out_adj  = out;                                        // 200*100*100
    float* out_mu   = out + (size_t)N_GRAPHS * MAXN * MAXN;       // 200*64
    float* out_lv   = out_mu + (size_t)N_GRAPHS * L_DIM;          // 200*64

    float *p_u, *p_h, *p_z, *p_d1, *p_d2;
    cudaGetSymbolAddress((void**)&p_u,  g_u);
    cudaGetSymbolAddress((void**)&p_h,  g_h);
    cudaGetSymbolAddress((void**)&p_z,  g_z);
    cudaGetSymbolAddress((void**)&p_d1, g_d1);
    cudaGetSymbolAddress((void**)&p_d2, g_d2);

    // Lazy-created side stream + events (first call is the uncaptured
    // correctness run; capture reuses them — no creation under capture).
    static cudaStream_t s_side = nullptr;
    static cudaEvent_t  ev_fork = nullptr, ev_join = nullptr;
    if (s_side == nullptr) {
        cudaStreamCreateWithFlags(&s_side, cudaStreamNonBlocking);
        cudaEventCreateWithFlags(&ev_fork, cudaEventDisableTiming);
        cudaEventCreateWithFlags(&ev_join, cudaEventDisableTiming);
    }

    // CSR prefix (dinv needed by gemm1 epilogue) on main stream
    zero_kernel<<<(N_GRAPHS * H_DIM + 255) / 256, 256>>>();
    hist_kernel<<<(N_EDGES + 255) / 256, 256>>>(dst);
    scan_kernel<<<1, SCAN_T>>>();

    // fork: fill + pairmap + diag run concurrently with gemm1
    cudaEventRecord(ev_fork, 0);
    cudaStreamWaitEvent(s_side, ev_fork, 0);
    fill_kernel<<<(N_EDGES + 255) / 256, 256, 0, s_side>>>(src, dst);
    pairmap_kernel<<<MAXN, 128, 0, s_side>>>();
    diag_kernel<<<N_GRAPHS, 128, 0, s_side>>>(out_adj);
    cudaEventRecord(ev_join, s_side);

    dim3 ggrid(H_DIM / TBN, (N_NODES + TBM - 1) / TBM);

    // conv1 gemm (needs only dinv) overlaps the side stream
    gemm_rowscale_kernel<<<ggrid, 256>>>(x, W1, p_u, N_NODES, IN_DIM, H_DIM);

    // join: gather needs the CSR fill
    cudaStreamWaitEvent(0, ev_join, 0);
    gather_relu_kernel<<<N_NODES, 64>>>(b1, p_h);

    // conv2: gemm -> gather fused with mean-pool accumulation
    gemm_rowscale_kernel<<<ggrid, 256>>>(p_h, W2, p_u, N_NODES, H_DIM, H_DIM);
    gather_pool_kernel<<<N_NODES, 64>>>(b2, batch);
    pool_div_kernel<<<N_GRAPHS, H_DIM>>>();

    // VAE head
    muz_kernel<<<N_GRAPHS, L_DIM>>>(Wmu, bmu, Wlv, blv, eps, out_mu, out_lv);

    // decoder MLP
    dense_relu_kernel<<<N_GRAPHS, H_DIM>>>(p_z,  D1, db1, p_d1, L_DIM);
    dense_relu_kernel<<<N_GRAPHS, H_DIM>>>(p_d1, D2, db2, p_d2, H_DIM);

    // adjacency
    adj_kernel<<<dim3((NPAIR + 127) / 128, N_GRAPHS / GCH), 128>>>(D3, db3, out_adj);
}

// round 13
// speedup vs baseline: 1.4125x; 1.2532x over previous
#include <cuda_runtime.h>
#include <cstdint>
#include <cmath>

// ---------------- problem constants ----------------
#define N_NODES   20000
#define N_EDGES   320000
#define N_GRAPHS  200
#define MAXN      100
#define NPAIR     4950          // 100*99/2
#define IN_DIM    128
#define H_DIM     256
#define L_DIM     64

// ---------------- scratch (device globals; no allocation allowed) ----------
__device__ __align__(128) int   g_hist[N_NODES];            // in-degree
__device__ __align__(128) int   g_off [N_NODES];            // CSR exclusive offsets
__device__ __align__(128) int   g_cur [N_NODES];            // fill cursors
__device__ __align__(128) int   g_csr [N_EDGES];            // src ids grouped by dst
__device__ __align__(128) float g_dinv[N_NODES];            // rsqrt(deg+1)
__device__ __align__(128) float g_u   [N_NODES * H_DIM];    // (A@W)*dinv[row]
__device__ __align__(128) float g_h   [N_NODES * H_DIM];    // conv1 output
__device__ __align__(128) float g_sums[N_GRAPHS * H_DIM];
__device__ __align__(128) float g_cnt [N_GRAPHS];
__device__ __align__(128) float g_hg  [N_GRAPHS * H_DIM];
__device__ __align__(128) float g_z   [N_GRAPHS * L_DIM];
__device__ __align__(128) float g_d1  [N_GRAPHS * H_DIM];
__device__ __align__(128) float g_d2  [N_GRAPHS * H_DIM];
__device__ __align__(128) int   g_pi  [NPAIR];
__device__ __align__(128) int   g_pj  [NPAIR];

// ---------------- zero scratch ----------------
__global__ void zero_kernel() {
    int i = blockIdx.x * blockDim.x + threadIdx.x;
    if (i < N_NODES) { g_hist[i] = 0; g_cur[i] = 0; }
    if (i < N_GRAPHS * H_DIM) g_sums[i] = 0.f;
    if (i < N_GRAPHS) g_cnt[i] = 0.f;
}

// ---------------- CSR build ----------------
__global__ void hist_kernel(const int* __restrict__ dst) {
    int e = blockIdx.x * blockDim.x + threadIdx.x;
    if (e < N_EDGES) atomicAdd(&g_hist[dst[e]], 1);
}

#define SCAN_T 1024
#define SCAN_CH 20   // 1024*20 >= 20000
__global__ __launch_bounds__(SCAN_T)
void scan_kernel() {
    __shared__ int sp[SCAN_T];
    int t = threadIdx.x;
    int start = t * SCAN_CH;
    int s = 0;
#pragma unroll
    for (int c = 0; c < SCAN_CH; c++) {
        int i = start + c;
        if (i < N_NODES) s += g_hist[i];
    }
    sp[t] = s;
    __syncthreads();
    for (int off = 1; off < SCAN_T; off <<= 1) {
        int v = (t >= off) ? sp[t - off] : 0;
        __syncthreads();
        sp[t] += v;
        __syncthreads();
    }
    int base = sp[t] - s;
#pragma unroll
    for (int c = 0; c < SCAN_CH; c++) {
        int i = start + c;
        if (i < N_NODES) { g_off[i] = base; base += g_hist[i]; }
    }
    for (int i = t; i < N_NODES; i += SCAN_T)
        g_dinv[i] = rsqrtf((float)g_hist[i] + 1.0f);
}

__global__ void fill_kernel(const int* __restrict__ src, const int* __restrict__ dst) {
    int e = blockIdx.x * blockDim.x + threadIdx.x;
    if (e >= N_EDGES) return;
    int d = dst[e];
    int pos = atomicAdd(&g_cur[d], 1);
    g_csr[g_off[d] + pos] = src[e];
}

// ---------------- tf32 MMA GEMM: U = (A@B) * dinv[row] --------------------
// 3-term split for fp32-class accuracy: D += Ahi*Bhi + Ahi*Blo + Alo*Bhi
#define BM 64
#define BN 64
#define BK 16
#define AP 20   // As pitch (conflict-free for A-fragment loads)
#define BP 72   // Bs pitch (conflict-free for B-fragment loads)

__device__ __forceinline__ uint32_t f2tf32(float x) {
    uint32_t r;
    asm("cvt.rna.tf32.f32 %0, %1;" : "=r"(r) : "f"(x));
    return r;
}
__device__ __forceinline__ void tf32_split(float x, uint32_t& hi, uint32_t& lo) {
    hi = f2tf32(x);
    float hf = __uint_as_float(hi);
    lo = f2tf32(x - hf);
}
__device__ __forceinline__ void mma_tf32(float* c, const uint32_t* a, const uint32_t* b) {
    asm volatile(
        "mma.sync.aligned.m16n8k8.row.col.f32.tf32.tf32.f32 "
        "{%0,%1,%2,%3},{%4,%5,%6,%7},{%8,%9},{%0,%1,%2,%3};"
        : "+f"(c[0]), "+f"(c[1]), "+f"(c[2]), "+f"(c[3])
        : "r"(a[0]), "r"(a[1]), "r"(a[2]), "r"(a[3]), "r"(b[0]), "r"(b[1]));
}

__global__ __launch_bounds__(128)
void gemm_tf32_rowscale_kernel(const float* __restrict__ A,
                               const float* __restrict__ B,
                               float* __restrict__ U,
                               int M, int K, int N) {
    __shared__ float As[BM][AP];
    __shared__ float Bs[BK][BP];
    const int bm   = blockIdx.y * BM;
    const int bn   = blockIdx.x * BN;
    const int tid  = threadIdx.x;
    const int wid  = tid >> 5;
    const int lane = tid & 31;
    const int wm   = wid >> 1;        // 0..1
    const int wn   = wid & 1;         // 0..1
    const int gid  = lane >> 2;       // 0..7
    const int tig  = lane & 3;        // 0..3

    float acc[2][4][4];
#pragma unroll
    for (int mt = 0; mt < 2; mt++)
#pragma unroll
        for (int nt = 0; nt < 4; nt++)
#pragma unroll
            for (int i = 0; i < 4; i++) acc[mt][nt][i] = 0.f;

    for (int k0 = 0; k0 < K; k0 += BK) {
        // A tile 64x16 (row-major slice)
#pragma unroll
        for (int l = 0; l < 2; l++) {
            int t = tid + l * 128;
            int r = t >> 2;
            int c = (t & 3) * 4;
            float4 v = make_float4(0.f, 0.f, 0.f, 0.f);
            if (bm + r < M)
                v = *reinterpret_cast<const float4*>(&A[(size_t)(bm + r) * K + k0 + c]);
            As[r][c + 0] = v.x; As[r][c + 1] = v.y;
            As[r][c + 2] = v.z; As[r][c + 3] = v.w;
        }
        // B tile 16x64
#pragma unroll
        for (int l = 0; l < 2; l++) {
            int t = tid + l * 128;
            int r = t >> 4;
            int c = (t & 15) * 4;
            float4 v = *reinterpret_cast<const float4*>(&B[(size_t)(k0 + r) * N + bn + c]);
            *reinterpret_cast<float4*>(&Bs[r][c]) = v;
        }
        __syncthreads();

#pragma unroll
        for (int ks = 0; ks < BK; ks += 8) {
            uint32_t ahi[2][4], alo[2][4], bhi[4][2], blo[4][2];
#pragma unroll
            for (int mt = 0; mt < 2; mt++) {
                int r0 = wm * 32 + mt * 16 + gid;
                tf32_split(As[r0    ][ks + tig    ], ahi[mt][0], alo[mt][0]);
                tf32_split(As[r0 + 8][ks + tig    ], ahi[mt][1], alo[mt][1]);
                tf32_split(As[r0    ][ks + tig + 4], ahi[mt][2], alo[mt][2]);
                tf32_split(As[r0 + 8][ks + tig + 4], ahi[mt][3], alo[mt][3]);
            }
#pragma unroll
            for (int nt = 0; nt < 4; nt++) {
                int n = wn * 32 + nt * 8 + gid;
                tf32_split(Bs[ks + tig    ][n], bhi[nt][0], blo[nt][0]);
                tf32_split(Bs[ks + tig + 4][n], bhi[nt][1], blo[nt][1]);
            }
#pragma unroll
            for (int mt = 0; mt < 2; mt++)
#pragma unroll
                for (int nt = 0; nt < 4; nt++) {
                    mma_tf32(acc[mt][nt], ahi[mt], bhi[nt]);
                    mma_tf32(acc[mt][nt], ahi[mt], blo[nt]);
                    mma_tf32(acc[mt][nt], alo[mt], bhi[nt]);
                }
        }
        __syncthreads();
    }

    // epilogue: rowscale by dinv, fragment layout c0/c1 = (row, 2*tig(+1)), c2/c3 = row+8
#pragma unroll
    for (int mt = 0; mt < 2; mt++) {
        int r0 = bm + wm * 32 + mt * 16 + gid;
        int r1 = r0 + 8;
        float rs0 = (r0 < M) ? g_dinv[r0] : 0.f;
        float rs1 = (r1 < M) ? g_dinv[r1] : 0.f;
#pragma unroll
        for (int nt = 0; nt < 4; nt++) {
            int c = bn + wn * 32 + nt * 8 + tig * 2;
            if (r0 < M) {
                float2 v0 = make_float2(acc[mt][nt][0] * rs0, acc[mt][nt][1] * rs0);
                *reinterpret_cast<float2*>(&U[(size_t)r0 * N + c]) = v0;
            }
            if (r1 < M) {
                float2 v1 = make_float2(acc[mt][nt][2] * rs1, acc[mt][nt][3] * rs1);
                *reinterpret_cast<float2*>(&U[(size_t)r1 * N + c]) = v1;
            }
        }
    }
}

// ---------------- CSR gather conv: h[m] = relu(dinv[m]*(u[m]+Σu[s]) + b) ---
__global__ __launch_bounds__(64)
void gather_relu_kernel(const float* __restrict__ bias, float* __restrict__ out) {
    int m = blockIdx.x;
    int f4 = threadIdx.x;                  // 0..63
    const float4* U4 = reinterpret_cast<const float4*>(g_u);
    int beg = g_off[m];
    int cnt = g_hist[m];
    float4 acc = U4[(size_t)m * 64 + f4];  // self loop
    int e = 0;
    for (; e + 4 <= cnt; e += 4) {
        int s0 = g_csr[beg + e + 0], s1 = g_csr[beg + e + 1];
        int s2 = g_csr[beg + e + 2], s3 = g_csr[beg + e + 3];
        float4 v0 = U4[(size_t)s0 * 64 + f4];
        float4 v1 = U4[(size_t)s1 * 64 + f4];
        float4 v2 = U4[(size_t)s2 * 64 + f4];
        float4 v3 = U4[(size_t)s3 * 64 + f4];
        acc.x += (v0.x + v1.x) + (v2.x + v3.x);
        acc.y += (v0.y + v1.y) + (v2.y + v3.y);
        acc.z += (v0.z + v1.z) + (v2.z + v3.z);
        acc.w += (v0.w + v1.w) + (v2.w + v3.w);
    }
    for (; e < cnt; e++) {
        int s = g_csr[beg + e];
        float4 v = U4[(size_t)s * 64 + f4];
        acc.x += v.x; acc.y += v.y; acc.z += v.z; acc.w += v.w;
    }
    float di = g_dinv[m];
    float4 bb = reinterpret_cast<const float4*>(bias)[f4];
    float4 h;
    h.x = fmaxf(di * acc.x + bb.x, 0.f);
    h.y = fmaxf(di * acc.y + bb.y, 0.f);
    h.z = fmaxf(di * acc.z + bb.z, 0.f);
    h.w = fmaxf(di * acc.w + bb.w, 0.f);
    reinterpret_cast<float4*>(out)[(size_t)m * 64 + f4] = h;
}

// conv2 gather fused with mean-pool accumulation (h never materialized)
__global__ __launch_bounds__(64)
void gather_pool_kernel(const float* __restrict__ bias, const int* __restrict__ batch) {
    int m = blockIdx.x;
    int f4 = threadIdx.x;
    const float4* U4 = reinterpret_cast<const float4*>(g_u);
    int beg = g_off[m];
    int cnt = g_hist[m];
    float4 acc = U4[(size_t)m * 64 + f4];
    int e = 0;
    for (; e + 4 <= cnt; e += 4) {
        int s0 = g_csr[beg + e + 0], s1 = g_csr[beg + e + 1];
        int s2 = g_csr[beg + e + 2], s3 = g_csr[beg + e + 3];
        float4 v0 = U4[(size_t)s0 * 64 + f4];
        float4 v1 = U4[(size_t)s1 * 64 + f4];
        float4 v2 = U4[(size_t)s2 * 64 + f4];
        float4 v3 = U4[(size_t)s3 * 64 + f4];
        acc.x += (v0.x + v1.x) + (v2.x + v3.x);
        acc.y += (v0.y + v1.y) + (v2.y + v3.y);
        acc.z += (v0.z + v1.z) + (v2.z + v3.z);
        acc.w += (v0.w + v1.w) + (v2.w + v3.w);
    }
    for (; e < cnt; e++) {
        int s = g_csr[beg + e];
        float4 v = U4[(size_t)s * 64 + f4];
        acc.x += v.x; acc.y += v.y; acc.z += v.z; acc.w += v.w;
    }
    float di = g_dinv[m];
    float4 bb = reinterpret_cast<const float4*>(bias)[f4];
    float hx = fmaxf(di * acc.x + bb.x, 0.f);
    float hy = fmaxf(di * acc.y + bb.y, 0.f);
    float hz = fmaxf(di * acc.z + bb.z, 0.f);
    float hw = fmaxf(di * acc.w + bb.w, 0.f);
    int b = batch[m];
    float* sbase = &g_sums[(size_t)b * H_DIM + f4 * 4];
    atomicAdd(sbase + 0, hx);
    atomicAdd(sbase + 1, hy);
    atomicAdd(sbase + 2, hz);
    atomicAdd(sbase + 3, hw);
    if (f4 == 0) atomicAdd(&g_cnt[b], 1.0f);
}

__global__ void pool_div_kernel() {
    int g = blockIdx.x;
    int f = threadIdx.x;
    g_hg[g * H_DIM + f] = g_sums[g * H_DIM + f] / fmaxf(g_cnt[g], 1.0f);
}

// ---------------- mu / logvar / z ----------------
__global__ void muz_kernel(const float* __restrict__ Wmu, const float* __restrict__ bmu,
                           const float* __restrict__ Wlv, const float* __restrict__ blv,
                           const float* __restrict__ eps,
                           float* __restrict__ out_mu, float* __restrict__ out_lv) {
    int g = blockIdx.x;
    int l = threadIdx.x;            // 64
    __shared__ float sh[H_DIM];
    for (int k = l; k < H_DIM; k += L_DIM) sh[k] = g_hg[g * H_DIM + k];
    __syncthreads();
    float mu = bmu[l], lv = blv[l];
    for (int k = 0; k < H_DIM; k++) {
        float h = sh[k];
        mu += h * Wmu[k * L_DIM + l];
        lv += h * Wlv[k * L_DIM + l];
    }
    out_mu[g * L_DIM + l] = mu;
    out_lv[g * L_DIM + l] = lv;
    g_z[g * L_DIM + l] = mu + eps[g * L_DIM + l] * expf(0.5f * lv);
}

// ---------------- decoder dense+relu ----------------
__global__ void dense_relu_kernel(const float* __restrict__ X,
                                  const float* __restrict__ W,
                                  const float* __restrict__ b,
                                  float* __restrict__ Y, int K) {
    int g = blockIdx.x;
    int n = threadIdx.x;            // 256
    __shared__ float sx[H_DIM];
    if (n < K) sx[n] = X[g * K + n];
    __syncthreads();
    float acc = b[n];
    for (int k = 0; k < K; k++) acc += sx[k] * W[k * H_DIM + n];
    Y[g * H_DIM + n] = fmaxf(acc, 0.f);
}

// ---------------- adjacency decode ----------------
__global__ void pairmap_kernel() {
    int i = blockIdx.x;             // 0..99
    int j = threadIdx.x;            // 0..127
    if (j > i && j < MAXN) {
        int p = i * 99 - (i * (i - 1)) / 2 + (j - i - 1);
        g_pi[p] = i;
        g_pj[p] = j;
    }
}

__global__ void diag_kernel(float* __restrict__ adj) {
    int g = blockIdx.x;
    int i = threadIdx.x;
    if (i < MAXN)
        adj[(size_t)g * MAXN * MAXN + i * MAXN + i] = 0.f;
}

#define GCH 8
__global__ __launch_bounds__(128)
void adj_kernel(const float* __restrict__ D3, const float* __restrict__ db3,
                float* __restrict__ adj) {
    int p  = blockIdx.x * 128 + threadIdx.x;
    int g0 = blockIdx.y * GCH;
    __shared__ float sd2[GCH][H_DIM];
    for (int idx = threadIdx.x; idx < GCH * H_DIM; idx += 128)
        sd2[idx >> 8][idx & 255] = g_d2[(size_t)(g0 + (idx >> 8)) * H_DIM + (idx & 255)];
    __syncthreads();
    if (p >= NPAIR) return;
    int i = g_pi[p], j = g_pj[p];
    float bb = db3[p];
    float acc[GCH];
#pragma unroll
    for (int gg = 0; gg < GCH; gg++) acc[gg] = bb;
    for (int k = 0; k < H_DIM; k++) {
        float w = D3[(size_t)k * NPAIR + p];
#pragma unroll
        for (int gg = 0; gg < GCH; gg++) acc[gg] += sd2[gg][k] * w;
    }
#pragma unroll
    for (int gg = 0; gg < GCH; gg++) {
        float prob = 1.0f / (1.0f + expf(-acc[gg]));
        size_t base = (size_t)(g0 + gg) * (MAXN * MAXN);
        adj[base + i * MAXN + j] = prob;
        adj[base + j * MAXN + i] = prob;
    }
}

// ---------------- launch ----------------
extern "C" void kernel_launch(void* const* d_in, const int* in_sizes, int n_in,
                              void* d_out, int out_size) {
    const float* x    = (const float*)d_in[0];
    const int*   ei   = (const int*)  d_in[1];
    const int*   batch= (const int*)  d_in[2];
    const float* eps  = (const float*)d_in[3];
    const float* W1   = (const float*)d_in[4];
    const float* b1   = (const float*)d_in[5];
    const float* W2   = (const float*)d_in[6];
    const float* b2   = (const float*)d_in[7];
    const float* Wmu  = (const float*)d_in[8];
    const float* bmu  = (const float*)d_in[9];
    const float* Wlv  = (const float*)d_in[10];
    const float* blv  = (const float*)d_in[11];
    const float* D1   = (const float*)d_in[12];
    const float* db1  = (const float*)d_in[13];
    const float* D2   = (const float*)d_in[14];
    const float* db2  = (const float*)d_in[15];
    const float* D3   = (const float*)d_in[16];
    const float* db3  = (const float*)d_in[17];

    const int* src = ei;
    const int* dst = ei + N_EDGES;

    float* out      = (float*)d_out;
    float* out_adj  = out;                                        // 200*100*100
    float* out_mu   = out + (size_t)N_GRAPHS * MAXN * MAXN;       // 200*64
    float* out_lv   = out_mu + (size_t)N_GRAPHS * L_DIM;          // 200*64

    float *p_u, *p_h, *p_z, *p_d1, *p_d2;
    cudaGetSymbolAddress((void**)&p_u,  g_u);
    cudaGetSymbolAddress((void**)&p_h,  g_h);
    cudaGetSymbolAddress((void**)&p_z,  g_z);
    cudaGetSymbolAddress((void**)&p_d1, g_d1);
    cudaGetSymbolAddress((void**)&p_d2, g_d2);

    // Lazy-created side stream + events (first call is the uncaptured
    // correctness run; capture reuses them — no creation under capture).
    static cudaStream_t s_side = nullptr;
    static cudaEvent_t  ev_fork = nullptr, ev_join = nullptr;
    if (s_side == nullptr) {
        cudaStreamCreateWithFlags(&s_side, cudaStreamNonBlocking);
        cudaEventCreateWithFlags(&ev_fork, cudaEventDisableTiming);
        cudaEventCreateWithFlags(&ev_join, cudaEventDisableTiming);
    }

    // CSR prefix (dinv needed by gemm1 epilogue) on main stream
    zero_kernel<<<(N_GRAPHS * H_DIM + 255) / 256, 256>>>();
    hist_kernel<<<(N_EDGES + 255) / 256, 256>>>(dst);
    scan_kernel<<<1, SCAN_T>>>();

    // fork: fill + pairmap + diag run concurrently with gemm1
    cudaEventRecord(ev_fork, 0);
    cudaStreamWaitEvent(s_side, ev_fork, 0);
    fill_kernel<<<(N_EDGES + 255) / 256, 256, 0, s_side>>>(src, dst);
    pairmap_kernel<<<MAXN, 128, 0, s_side>>>();
    diag_kernel<<<N_GRAPHS, 128, 0, s_side>>>(out_adj);
    cudaEventRecord(ev_join, s_side);

    dim3 ggrid(H_DIM / BN, (N_NODES + BM - 1) / BM);

    // conv1 gemm (needs only dinv) overlaps the side stream
    gemm_tf32_rowscale_kernel<<<ggrid, 128>>>(x, W1, p_u, N_NODES, IN_DIM, H_DIM);

    // join: gather needs the CSR fill
    cudaStreamWaitEvent(0, ev_join, 0);
    gather_relu_kernel<<<N_NODES, 64>>>(b1, p_h);

    // conv2: gemm -> gather fused with mean-pool accumulation
    gemm_tf32_rowscale_kernel<<<ggrid, 128>>>(p_h, W2, p_u, N_NODES, H_DIM, H_DIM);
    gather_pool_kernel<<<N_NODES, 64>>>(b2, batch);
    pool_div_kernel<<<N_GRAPHS, H_DIM>>>();

    // VAE head
    muz_kernel<<<N_GRAPHS, L_DIM>>>(Wmu, bmu, Wlv, blv, eps, out_mu, out_lv);

    // decoder MLP
    dense_relu_kernel<<<N_GRAPHS, H_DIM>>>(p_z,  D1, db1, p_d1, L_DIM);
    dense_relu_kernel<<<N_GRAPHS, H_DIM>>>(p_d1, D2, db2, p_d2, H_DIM);

    // adjacency
    adj_kernel<<<dim3((NPAIR + 127) / 128, N_GRAPHS / GCH), 128>>>(D3, db3, out_adj);
}